// round 14
// baseline (speedup 1.0000x reference)
#include <cuda_runtime.h>
#include <cuda_bf16.h>
#include <math.h>
#include <cstdint>

#define kS  1024
#define kB  4
#define kD  1024
#define kH  16
#define kDH 64

// ---- int8 two-level quant scratch (projection inputs) ----
__device__ int8_t g_a1[3][kS*kB*kD];      // activation hi bytes  [which][row=s*B+b][k]
__device__ int8_t g_a0[3][kS*kB*kD];      // activation lo bytes
__device__ float  g_isa[3][kS*kB];        // 1/Sa per activation row
__device__ float  g_wt[3][kH*kDH*kD];     // fp32 transposed weights [which][h*64+n][k]
__device__ int8_t g_w1[3][kH*kDH*kD];     // weight hi bytes
__device__ int8_t g_w0[3][kH*kDH*kD];     // weight lo bytes
__device__ float  g_isw[3][kH*kDH];       // 1/Sw per weight n-row

// ---- bf16 split scratch (attention + output projection, unchanged) ----
__device__ __nv_bfloat16 g_oa_hi[kS*kB*kD], g_oa_lo[kS*kB*kD];   // attn out (concat)
__device__ __nv_bfloat16 g_wo_hi[kD*kD],     g_wo_lo[kD*kD];     // [n][k]
__device__ __nv_bfloat16 g_qp_hi[kB*kH*kS*kDH], g_qp_lo[kB*kH*kS*kDH]; // [b][h][s][dh]
__device__ __nv_bfloat16 g_kp_hi[kB*kH*kS*kDH], g_kp_lo[kB*kH*kS*kDH]; // [b][h][s][dh]
__device__ __nv_bfloat16 g_vp_hi[kB*kH*kS*kDH], g_vp_lo[kB*kH*kS*kDH]; // [b][h][dh][s]

// ===================== helpers =====================
__device__ __forceinline__ uint32_t smem_u32(const void* p) {
    uint32_t a;
    asm("{ .reg .u64 t; cvta.to.shared.u64 t, %1; cvt.u32.u64 %0, t; }" : "=r"(a) : "l"(p));
    return a;
}
__device__ __forceinline__ void ldmatrix_x4(uint32_t* r, uint32_t a) {
    asm volatile("ldmatrix.sync.aligned.m8n8.x4.shared.b16 {%0,%1,%2,%3}, [%4];"
        : "=r"(r[0]), "=r"(r[1]), "=r"(r[2]), "=r"(r[3]) : "r"(a));
}
__device__ __forceinline__ void mma_bf16(float* c, const uint32_t* a, const uint32_t* b) {
    asm volatile("mma.sync.aligned.m16n8k16.row.col.f32.bf16.bf16.f32 "
        "{%0,%1,%2,%3},{%4,%5,%6,%7},{%8,%9},{%0,%1,%2,%3};"
        : "+f"(c[0]), "+f"(c[1]), "+f"(c[2]), "+f"(c[3])
        : "r"(a[0]), "r"(a[1]), "r"(a[2]), "r"(a[3]), "r"(b[0]), "r"(b[1]));
}
__device__ __forceinline__ void mma_s8(int* c, const uint32_t* a, const uint32_t* b) {
    asm volatile("mma.sync.aligned.m16n8k32.row.col.s32.s8.s8.s32 "
        "{%0,%1,%2,%3},{%4,%5,%6,%7},{%8,%9},{%0,%1,%2,%3};"
        : "+r"(c[0]), "+r"(c[1]), "+r"(c[2]), "+r"(c[3])
        : "r"(a[0]), "r"(a[1]), "r"(a[2]), "r"(a[3]), "r"(b[0]), "r"(b[1]));
}
__device__ __forceinline__ void split_pack(float x, float y, uint32_t& hp, uint32_t& lp) {
    __nv_bfloat16 hx = __float2bfloat16_rn(x);
    __nv_bfloat16 hy = __float2bfloat16_rn(y);
    __nv_bfloat16 lx = __float2bfloat16_rn(x - __bfloat162float(hx));
    __nv_bfloat16 ly = __float2bfloat16_rn(y - __bfloat162float(hy));
    hp = (uint32_t)__bfloat16_as_ushort(hx) | ((uint32_t)__bfloat16_as_ushort(hy) << 16);
    lp = (uint32_t)__bfloat16_as_ushort(lx) | ((uint32_t)__bfloat16_as_ushort(ly) << 16);
}
__device__ __forceinline__ void cp_async16(uint32_t saddr, const void* gptr) {
    asm volatile("cp.async.cg.shared.global [%0], [%1], 16;" :: "r"(saddr), "l"(gptr));
}
#define CP_COMMIT() asm volatile("cp.async.commit_group;" ::: "memory")
#define CP_WAIT_0() asm volatile("cp.async.wait_group 0;" ::: "memory")

// swizzled offset within a 128B-row tile: row-major, seg XOR (row&7)
__device__ __forceinline__ uint32_t sw_off(int row, int seg) {
    return (uint32_t)(row * 128 + ((seg ^ (row & 7)) << 4));
}

#define QCAP 16256.0f

// quantize one 1024-float row into (hi,lo) int8 with per-row scale. 256 thr.
__device__ __forceinline__ void quant_row_256(
    const float* __restrict__ row, int tid,
    int8_t* __restrict__ d1, int8_t* __restrict__ d0,
    float* __restrict__ inv_scale_out)
{
    __shared__ float red[8];
    float4 v = ((const float4*)row)[tid];
    float m = fmaxf(fmaxf(fabsf(v.x), fabsf(v.y)), fmaxf(fabsf(v.z), fabsf(v.w)));
    #pragma unroll
    for (int o = 16; o > 0; o >>= 1) m = fmaxf(m, __shfl_xor_sync(0xffffffffu, m, o));
    if ((tid & 31) == 0) red[tid >> 5] = m;
    __syncthreads();
    float mv = red[0];
    #pragma unroll
    for (int j = 1; j < 8; j++) mv = fmaxf(mv, red[j]);
    mv = fmaxf(mv, 1e-30f);
    float S = QCAP / mv;
    float f[4] = {v.x, v.y, v.z, v.w};
    uint32_t p1 = 0, p0 = 0;
    #pragma unroll
    for (int j = 0; j < 4; j++) {
        float as = f[j] * S;
        int q1 = __float2int_rn(as * (1.0f / 128.0f));
        int q0 = __float2int_rn(as - 128.0f * (float)q1);
        p1 |= ((uint32_t)q1 & 0xffu) << (8 * j);
        p0 |= ((uint32_t)q0 & 0xffu) << (8 * j);
    }
    ((uint32_t*)d1)[tid] = p1;
    ((uint32_t*)d0)[tid] = p0;
    if (tid == 0) *inv_scale_out = mv * (1.0f / QCAP);
}

// ===========================================================================
// Prep: quantize activations. grid (4096, 3)
// ===========================================================================
__global__ void __launch_bounds__(256) quant_act_kernel(
    const float* __restrict__ q, const float* __restrict__ k,
    const float* __restrict__ v)
{
    int which = blockIdx.y;
    int row = blockIdx.x;   // s*kB + b
    const float* src = ((which == 0) ? q : (which == 1) ? k : v) + (size_t)row * kD;
    quant_row_256(src, threadIdx.x,
                  g_a1[which] + (size_t)row * kD,
                  g_a0[which] + (size_t)row * kD,
                  &g_isa[which][row]);
}

// ===========================================================================
// Prep: transpose Wq/Wk/Wv to fp32 [h][n][k], then quantize rows.
// ===========================================================================
__global__ void __launch_bounds__(256) transpose_wqkv_f32_kernel(
    const float* __restrict__ Wq, const float* __restrict__ Wk,
    const float* __restrict__ Wv)
{
    __shared__ float tile[32][33];
    int which = blockIdx.z >> 4;
    int h = blockIdx.z & 15;
    const float* src = ((which == 0) ? Wq : (which == 1) ? Wk : Wv) + (size_t)h * kD * kDH;
    float* dst = g_wt[which] + (size_t)h * kDH * kD;
    int c0 = blockIdx.x * 32, r0 = blockIdx.y * 32;
    int tx = threadIdx.x, ty = threadIdx.y;
    #pragma unroll
    for (int i = 0; i < 4; i++)
        tile[ty + i * 8][tx] = src[(size_t)(r0 + ty + i * 8) * kDH + c0 + tx];
    __syncthreads();
    #pragma unroll
    for (int i = 0; i < 4; i++)
        dst[(size_t)(c0 + ty + i * 8) * kD + r0 + tx] = tile[tx][ty + i * 8];
}

__global__ void __launch_bounds__(256) quant_w_kernel()
{
    int which = blockIdx.y;
    int row = blockIdx.x;   // h*64 + n
    const float* src = g_wt[which] + (size_t)row * kD;
    quant_row_256(src, threadIdx.x,
                  g_w1[which] + (size_t)row * kD,
                  g_w0[which] + (size_t)row * kD,
                  &g_isw[which][row]);
}

// Wo [D][D] -> bf16 split [n][k] (outproj unchanged). grid (32,32)
__global__ void __launch_bounds__(256) transpose_wo_kernel(const float* __restrict__ Wo)
{
    __shared__ float tile[32][33];
    int c0 = blockIdx.x * 32, r0 = blockIdx.y * 32;
    int tx = threadIdx.x, ty = threadIdx.y;
    #pragma unroll
    for (int i = 0; i < 4; i++)
        tile[ty + i * 8][tx] = Wo[(size_t)(r0 + ty + i * 8) * kD + c0 + tx];
    __syncthreads();
    #pragma unroll
    for (int i = 0; i < 4; i++) {
        float v = tile[tx][ty + i * 8];
        __nv_bfloat16 hv = __float2bfloat16_rn(v);
        __nv_bfloat16 lv = __float2bfloat16_rn(v - __bfloat162float(hv));
        size_t o = (size_t)(c0 + ty + i * 8) * kD + r0 + tx;
        g_wo_hi[o] = hv;
        g_wo_lo[o] = lv;
    }
}

// ===========================================================================
// int8 projection GEMM: BM=128, BN=64 (=1 head), BK=64, 256 thr (8 warps 4x2).
// smem rows 128B = [64B hi (segs 0-3) | 64B lo (segs 4-7)], XOR swizzle.
// Stage: A 128 rows (16KB) @0, B 64 rows (8KB) @16384; 2 stages = 48KB.
// Per K=32 step: 3 s8 mma per (mt,nt): a1b1 -> acc1, a1b0 + a0b1 -> acc2.
// out = (16384*acc1 + 128*acc2) * isa[row] * isw[col] + bias   (exact int acc)
// ===========================================================================
#define P_A 0
#define P_B 16384
#define P_STG 24576
#define PROJ_SMEM (2 * P_STG)   // 49152

__global__ void __launch_bounds__(256, 2) proj_mma_kernel(
    const float* __restrict__ bq, const float* __restrict__ bk,
    const float* __restrict__ bv)
{
    extern __shared__ char smem[];
    uint32_t sbase = smem_u32(smem);
    int s0 = blockIdx.x * 128;
    int which = blockIdx.y >> 4;
    int h  = blockIdx.y & 15;
    int b  = blockIdx.z;
    int tid = threadIdx.x;
    int wid = tid >> 5, lane = tid & 31;
    int wm = wid >> 1, wn = wid & 1;
    int lrow = lane & 15, lseg = lane >> 4;

    const int8_t* a1p = g_a1[which];
    const int8_t* a0p = g_a0[which];
    const int8_t* w1p = g_w1[which];
    const int8_t* w0p = g_w0[which];
    const float* isa = g_isa[which];
    const float* isw = g_isw[which];
    const float* bias = (which == 0) ? bq : (which == 1) ? bk : bv;

    int acc1[2][4][4], acc2[2][4][4];
    #pragma unroll
    for (int mt = 0; mt < 2; mt++)
        #pragma unroll
        for (int nt = 0; nt < 4; nt++)
            #pragma unroll
            for (int e = 0; e < 4; e++) { acc1[mt][nt][e] = 0; acc2[mt][nt][e] = 0; }

    auto load_chunk = [&](int c, int stg) {
        uint32_t stb = sbase + stg * P_STG;
        int k0 = c * 64;
        #pragma unroll
        for (int i = 0; i < 2; i++) {
            int id = tid + i * 256;        // 0..511
            int m = id >> 2, s = id & 3;   // row, hi-seg
            size_t g = ((size_t)(s0 + m) * kB + b) * kD + k0 + s * 16;
            cp_async16(stb + P_A + sw_off(m, s), a1p + g);
            cp_async16(stb + P_A + sw_off(m, s + 4), a0p + g);
        }
        {
            int n = tid >> 2, s = tid & 3;
            size_t g = ((size_t)h * kDH + n) * kD + k0 + s * 16;
            cp_async16(stb + P_B + sw_off(n, s), w1p + g);
            cp_async16(stb + P_B + sw_off(n, s + 4), w0p + g);
        }
    };

    load_chunk(0, 0);
    CP_COMMIT();
    for (int c = 0; c < 16; c++) {
        CP_WAIT_0();
        __syncthreads();
        if (c + 1 < 16) {
            load_chunk(c + 1, (c + 1) & 1);
            CP_COMMIT();
        }
        uint32_t stb = sbase + (c & 1) * P_STG;
        #pragma unroll
        for (int ks = 0; ks < 2; ks++) {
            int seg = ks * 2 + lseg;
            uint32_t a1f[2][4], a0f[2][4], b1f[4][2], b0f[4][2];
            #pragma unroll
            for (int mt = 0; mt < 2; mt++) {
                int row = wm * 32 + mt * 16 + lrow;
                ldmatrix_x4(a1f[mt], stb + P_A + sw_off(row, seg));
                ldmatrix_x4(a0f[mt], stb + P_A + sw_off(row, seg + 4));
            }
            #pragma unroll
            for (int nt2 = 0; nt2 < 2; nt2++) {
                int row = wn * 32 + nt2 * 16 + lrow;
                uint32_t t[4], u[4];
                ldmatrix_x4(t, stb + P_B + sw_off(row, seg));
                b1f[nt2 * 2 + 0][0] = t[0]; b1f[nt2 * 2 + 0][1] = t[2];
                b1f[nt2 * 2 + 1][0] = t[1]; b1f[nt2 * 2 + 1][1] = t[3];
                ldmatrix_x4(u, stb + P_B + sw_off(row, seg + 4));
                b0f[nt2 * 2 + 0][0] = u[0]; b0f[nt2 * 2 + 0][1] = u[2];
                b0f[nt2 * 2 + 1][0] = u[1]; b0f[nt2 * 2 + 1][1] = u[3];
            }
            #pragma unroll
            for (int mt = 0; mt < 2; mt++)
                #pragma unroll
                for (int nt = 0; nt < 4; nt++) {
                    mma_s8(acc1[mt][nt], a1f[mt], b1f[nt]);
                    mma_s8(acc2[mt][nt], a1f[mt], b0f[nt]);
                    mma_s8(acc2[mt][nt], a0f[mt], b1f[nt]);
                }
        }
    }

    int gq = lane >> 2, tg = lane & 3;
    size_t bh = (size_t)b * kH + h;
    if (which < 2) {
        __nv_bfloat16* oh = (which == 0) ? g_qp_hi : g_kp_hi;
        __nv_bfloat16* ol = (which == 0) ? g_qp_lo : g_kp_lo;
        #pragma unroll
        for (int mt = 0; mt < 2; mt++) {
            int rl0 = wm * 32 + mt * 16 + gq;
            float ia0 = isa[(size_t)(s0 + rl0) * kB + b];
            float ia1 = isa[(size_t)(s0 + rl0 + 8) * kB + b];
            #pragma unroll
            for (int nt = 0; nt < 4; nt++) {
                int col = wn * 32 + nt * 8 + tg * 2;
                float iw0 = isw[h * kDH + col], iw1 = isw[h * kDH + col + 1];
                float b0 = bias[h * kDH + col], b1 = bias[h * kDH + col + 1];
                float v00 = (16384.f * (float)acc1[mt][nt][0] + 128.f * (float)acc2[mt][nt][0]) * (ia0 * iw0) + b0;
                float v01 = (16384.f * (float)acc1[mt][nt][1] + 128.f * (float)acc2[mt][nt][1]) * (ia0 * iw1) + b1;
                float v10 = (16384.f * (float)acc1[mt][nt][2] + 128.f * (float)acc2[mt][nt][2]) * (ia1 * iw0) + b0;
                float v11 = (16384.f * (float)acc1[mt][nt][3] + 128.f * (float)acc2[mt][nt][3]) * (ia1 * iw1) + b1;
                uint32_t hpk, lpk;
                size_t off0 = (bh * kS + s0 + rl0) * kDH + col;
                split_pack(v00, v01, hpk, lpk);
                *(uint32_t*)(oh + off0) = hpk; *(uint32_t*)(ol + off0) = lpk;
                split_pack(v10, v11, hpk, lpk);
                size_t off1 = off0 + (size_t)8 * kDH;
                *(uint32_t*)(oh + off1) = hpk; *(uint32_t*)(ol + off1) = lpk;
            }
        }
    } else {
        // V transposed: [b][h][dh][s]
        #pragma unroll
        for (int mt = 0; mt < 2; mt++) {
            int rl0 = wm * 32 + mt * 16 + gq;
            float ia0 = isa[(size_t)(s0 + rl0) * kB + b];
            float ia1 = isa[(size_t)(s0 + rl0 + 8) * kB + b];
            #pragma unroll
            for (int nt = 0; nt < 4; nt++) {
                int col = wn * 32 + nt * 8 + tg * 2;
                float iw0 = isw[h * kDH + col], iw1 = isw[h * kDH + col + 1];
                float b0 = bias[h * kDH + col], b1 = bias[h * kDH + col + 1];
                float vals[4];
                vals[0] = (16384.f * (float)acc1[mt][nt][0] + 128.f * (float)acc2[mt][nt][0]) * (ia0 * iw0) + b0;
                vals[1] = (16384.f * (float)acc1[mt][nt][1] + 128.f * (float)acc2[mt][nt][1]) * (ia0 * iw1) + b1;
                vals[2] = (16384.f * (float)acc1[mt][nt][2] + 128.f * (float)acc2[mt][nt][2]) * (ia1 * iw0) + b0;
                vals[3] = (16384.f * (float)acc1[mt][nt][3] + 128.f * (float)acc2[mt][nt][3]) * (ia1 * iw1) + b1;
                int rr[4] = {s0 + rl0, s0 + rl0, s0 + rl0 + 8, s0 + rl0 + 8};
                int cc[4] = {col, col + 1, col, col + 1};
                #pragma unroll
                for (int e = 0; e < 4; e++) {
                    __nv_bfloat16 hv = __float2bfloat16_rn(vals[e]);
                    __nv_bfloat16 lv = __float2bfloat16_rn(vals[e] - __bfloat162float(hv));
                    size_t off = (bh * kDH + cc[e]) * kS + rr[e];
                    g_vp_hi[off] = hv;
                    g_vp_lo[off] = lv;
                }
            }
        }
    }
}

// ===========================================================================
// bf16 GEMM compute (output projection) — round-12 proven version.
// ===========================================================================
#define SA0 0
#define SA1 16384
#define SB0 32768
#define SB1 40960
#define STG_SZ 49152
#define GEMM_SMEM (2 * STG_SZ)   // 98304

__device__ __forceinline__ void gemm_compute_chunk(
    uint32_t stb, int wm, int wn, int lane, float acc[2][4][4])
{
    int lrow = lane & 15;
    int lseg = lane >> 4;
    #pragma unroll
    for (int ks = 0; ks < 4; ks++) {
        int seg = ks * 2 + lseg;
        uint32_t a0f[2][4], a1f[2][4], b0f[4][2], b1f[4][2];
        #pragma unroll
        for (int mt = 0; mt < 2; mt++) {
            uint32_t addr = stb + SA0 + sw_off(wm * 32 + mt * 16 + lrow, seg);
            ldmatrix_x4(a0f[mt], addr);
            ldmatrix_x4(a1f[mt], addr + (SA1 - SA0));
        }
        #pragma unroll
        for (int nt2 = 0; nt2 < 2; nt2++) {
            uint32_t addr = stb + SB0 + sw_off(wn * 32 + nt2 * 16 + lrow, seg);
            uint32_t t[4];
            ldmatrix_x4(t, addr);
            b0f[nt2 * 2 + 0][0] = t[0]; b0f[nt2 * 2 + 0][1] = t[2];
            b0f[nt2 * 2 + 1][0] = t[1]; b0f[nt2 * 2 + 1][1] = t[3];
            ldmatrix_x4(t, addr + (SB1 - SB0));
            b1f[nt2 * 2 + 0][0] = t[0]; b1f[nt2 * 2 + 0][1] = t[2];
            b1f[nt2 * 2 + 1][0] = t[1]; b1f[nt2 * 2 + 1][1] = t[3];
        }
        #pragma unroll
        for (int mt = 0; mt < 2; mt++)
            #pragma unroll
            for (int nt = 0; nt < 4; nt++) {
                mma_bf16(acc[mt][nt], a0f[mt], b0f[nt]);
                mma_bf16(acc[mt][nt], a0f[mt], b1f[nt]);
                mma_bf16(acc[mt][nt], a1f[mt], b0f[nt]);
            }
    }
}

__global__ void __launch_bounds__(256) outproj_mma_kernel(
    const float* __restrict__ bo, float* __restrict__ out)
{
    extern __shared__ char smem[];
    uint32_t sbase = smem_u32(smem);
    int m0 = blockIdx.x * 128;
    int n0 = blockIdx.y * 64;
    int tid = threadIdx.x;
    int wid = tid >> 5, lane = tid & 31;
    int wm = wid >> 1, wn = wid & 1;

    float acc[2][4][4];
    #pragma unroll
    for (int mt = 0; mt < 2; mt++)
        #pragma unroll
        for (int nt = 0; nt < 4; nt++)
            #pragma unroll
            for (int e = 0; e < 4; e++) acc[mt][nt][e] = 0.f;

    auto load_chunk = [&](int c, int stg) {
        uint32_t stb = sbase + stg * STG_SZ;
        int k0 = c * 64;
        #pragma unroll
        for (int i = 0; i < 4; i++) {
            int id = tid + i * 256;
            int m = id >> 3, k8 = id & 7;
            size_t g = (size_t)(m0 + m) * kD + k0 + k8 * 8;
            uint32_t d = stb + sw_off(m, k8);
            cp_async16(d + SA0, g_oa_hi + g);
            cp_async16(d + SA1, g_oa_lo + g);
        }
        #pragma unroll
        for (int i = 0; i < 2; i++) {
            int id = tid + i * 256;
            int n = id >> 3, k8 = id & 7;
            size_t g = (size_t)(n0 + n) * kD + k0 + k8 * 8;
            uint32_t d = stb + sw_off(n, k8);
            cp_async16(d + SB0, g_wo_hi + g);
            cp_async16(d + SB1, g_wo_lo + g);
        }
    };

    load_chunk(0, 0);
    CP_COMMIT();
    for (int c = 0; c < 16; c++) {
        CP_WAIT_0();
        __syncthreads();
        if (c + 1 < 16) {
            load_chunk(c + 1, (c + 1) & 1);
            CP_COMMIT();
        }
        gemm_compute_chunk(sbase + (c & 1) * STG_SZ, wm, wn, lane, acc);
    }

    int gq = lane >> 2, tg = lane & 3;
    #pragma unroll
    for (int mt = 0; mt < 2; mt++) {
        int row = m0 + wm * 32 + mt * 16 + gq;
        #pragma unroll
        for (int nt = 0; nt < 4; nt++) {
            int col = n0 + wn * 32 + nt * 8 + tg * 2;
            float b0 = bo[col], b1 = bo[col + 1];
            size_t r0 = (size_t)row * kD + col;
            *(float2*)(out + r0) = make_float2(acc[mt][nt][0] + b0, acc[mt][nt][1] + b1);
            *(float2*)(out + r0 + 8 * kD) = make_float2(acc[mt][nt][2] + b0, acc[mt][nt][3] + b1);
        }
    }
}

// ===========================================================================
// Tensor-core attention — round-12 proven version (2-stage, 1 sync/tile).
// ===========================================================================
#define AK_HI 0
#define AK_LO 8192
#define AV_HI 16384
#define AV_LO 24576
#define ASTG  32768
#define AMK   65536
#define ATTN_SMEM (65536 + 4096)

__global__ void __launch_bounds__(256) attn_mma_kernel(const int* __restrict__ mask)
{
    extern __shared__ char smem[];
    uint32_t sbase = smem_u32(smem);
    int s0 = blockIdx.x * 128;
    int h  = blockIdx.y;
    int b  = blockIdx.z;
    int tid = threadIdx.x;
    int w = tid >> 5, lane = tid & 31;
    int gq = lane >> 2, tg = lane & 3;
    size_t bh = (size_t)b * kH + h;

    const __nv_bfloat16* qh = g_qp_hi + bh * kS * kDH;
    const __nv_bfloat16* ql = g_qp_lo + bh * kS * kDH;
    const __nv_bfloat16* kh = g_kp_hi + bh * kS * kDH;
    const __nv_bfloat16* kl = g_kp_lo + bh * kS * kDH;
    const __nv_bfloat16* vth = g_vp_hi + bh * kDH * kS;  // [dh][s]
    const __nv_bfloat16* vtl = g_vp_lo + bh * kDH * kS;

    float* Mk = (float*)(smem + AMK);
    for (int idx = tid; idx < kS; idx += 256)
        Mk[idx] = (float)mask[(size_t)idx * kB + b] * 1e18f;

    #pragma unroll
    for (int i = 0; i < 4; i++) {
        int id = tid + i * 256;
        int row = id >> 3, k8 = id & 7;
        size_t g = (size_t)(s0 + row) * kDH + k8 * 8;
        uint32_t d = sbase + sw_off(row, k8);
        cp_async16(d, qh + g);
        cp_async16(d + 16384, ql + g);
    }
    CP_COMMIT();
    CP_WAIT_0();
    __syncthreads();
    uint32_t qfh[4][4], qfl[4][4];
    int lrow = lane & 15, lseg = lane >> 4;
    #pragma unroll
    for (int ks = 0; ks < 4; ks++) {
        uint32_t addr = sbase + sw_off(w * 16 + lrow, ks * 2 + lseg);
        ldmatrix_x4(qfh[ks], addr);
        ldmatrix_x4(qfl[ks], addr + 16384);
    }
    __syncthreads();

    float acc_o[8][4];
    #pragma unroll
    for (int nt = 0; nt < 8; nt++)
        #pragma unroll
        for (int e = 0; e < 4; e++) acc_o[nt][e] = 0.f;
    float l_run[2] = {0.f, 0.f};
    const float scale = 0.125f;

    auto load_tile = [&](int t, int stg) {
        uint32_t stb = sbase + stg * ASTG;
        int j0 = t * 64;
        #pragma unroll
        for (int i = 0; i < 8; i++) {
            int id = tid + (i & 1) * 256;
            int row = id >> 3, k8 = id & 7;
            const __nv_bfloat16* src;
            uint32_t dst;
            if (i < 2)      { src = kh  + (size_t)(j0 + row) * kDH + k8 * 8; dst = AK_HI; }
            else if (i < 4) { src = kl  + (size_t)(j0 + row) * kDH + k8 * 8; dst = AK_LO; }
            else if (i < 6) { src = vth + (size_t)row * kS + j0 + k8 * 8;    dst = AV_HI; }
            else            { src = vtl + (size_t)row * kS + j0 + k8 * 8;    dst = AV_LO; }
            cp_async16(stb + dst + sw_off(row, k8), src);
        }
    };

    load_tile(0, 0);
    CP_COMMIT();
    for (int t = 0; t < 16; t++) {
        CP_WAIT_0();
        __syncthreads();
        if (t + 1 < 16) {
            load_tile(t + 1, (t + 1) & 1);
            CP_COMMIT();
        }
        uint32_t stb = sbase + (t & 1) * ASTG;
        int j0 = t * 64;

        float ps[8][4];
        #pragma unroll
        for (int nt = 0; nt < 8; nt++)
            #pragma unroll
            for (int e = 0; e < 4; e++) ps[nt][e] = 0.f;
        #pragma unroll
        for (int ks = 0; ks < 4; ks++) {
            int seg = ks * 2 + lseg;
            #pragma unroll
            for (int nt2 = 0; nt2 < 4; nt2++) {
                uint32_t addr = stb + AK_HI + sw_off(nt2 * 16 + lrow, seg);
                uint32_t tt[4], u[4];
                ldmatrix_x4(tt, addr);
                ldmatrix_x4(u, addr + (AK_LO - AK_HI));
                uint32_t bh0[2] = {tt[0], tt[2]}, bh1[2] = {tt[1], tt[3]};
                uint32_t bl0[2] = {u[0], u[2]}, bl1[2] = {u[1], u[3]};
                mma_bf16(ps[nt2 * 2 + 0], qfh[ks], bh0);
                mma_bf16(ps[nt2 * 2 + 0], qfh[ks], bl0);
                mma_bf16(ps[nt2 * 2 + 0], qfl[ks], bh0);
                mma_bf16(ps[nt2 * 2 + 1], qfh[ks], bh1);
                mma_bf16(ps[nt2 * 2 + 1], qfh[ks], bl1);
                mma_bf16(ps[nt2 * 2 + 1], qfl[ks], bh1);
            }
        }

        float l0 = 0.f, l1 = 0.f;
        #pragma unroll
        for (int nt = 0; nt < 8; nt++) {
            float mk0 = Mk[j0 + nt * 8 + tg * 2], mk1 = Mk[j0 + nt * 8 + tg * 2 + 1];
            float p0 = __expf(fminf(ps[nt][0] * scale - mk0, 60.f));
            float p1 = __expf(fminf(ps[nt][1] * scale - mk1, 60.f));
            float p2 = __expf(fminf(ps[nt][2] * scale - mk0, 60.f));
            float p3 = __expf(fminf(ps[nt][3] * scale - mk1, 60.f));
            l0 += p0 + p1; l1 += p2 + p3;
            ps[nt][0] = p0; ps[nt][1] = p1; ps[nt][2] = p2; ps[nt][3] = p3;
        }
        l_run[0] += l0; l_run[1] += l1;

        #pragma unroll
        for (int ks = 0; ks < 4; ks++) {
            uint32_t pah[4], pal[4];
            split_pack(ps[2 * ks + 0][0], ps[2 * ks + 0][1], pah[0], pal[0]);
            split_pack(ps[2 * ks + 0][2], ps[2 * ks + 0][3], pah[1], pal[1]);
            split_pack(ps[2 * ks + 1][0], ps[2 * ks + 1][1], pah[2], pal[2]);
            split_pack(ps[2 * ks + 1][2], ps[2 * ks + 1][3], pah[3], pal[3]);
            int seg = ks * 2 + lseg;
            #pragma unroll
            for (int nd2 = 0; nd2 < 4; nd2++) {
                uint32_t addr = stb + AV_HI + sw_off(nd2 * 16 + lrow, seg);
                uint32_t tt[4], u[4];
                ldmatrix_x4(tt, addr);
                ldmatrix_x4(u, addr + (AV_LO - AV_HI));
                uint32_t bh0[2] = {tt[0], tt[2]}, bh1[2] = {tt[1], tt[3]};
                uint32_t bl0[2] = {u[0], u[2]}, bl1[2] = {u[1], u[3]};
                mma_bf16(acc_o[nd2 * 2 + 0], pah, bh0);
                mma_bf16(acc_o[nd2 * 2 + 0], pah, bl0);
                mma_bf16(acc_o[nd2 * 2 + 0], pal, bh0);
                mma_bf16(acc_o[nd2 * 2 + 1], pah, bh1);
                mma_bf16(acc_o[nd2 * 2 + 1], pah, bl1);
                mma_bf16(acc_o[nd2 * 2 + 1], pal, bh1);
            }
        }
    }

    #pragma unroll
    for (int off = 1; off <= 2; off <<= 1) {
        l_run[0] += __shfl_xor_sync(0xffffffffu, l_run[0], off);
        l_run[1] += __shfl_xor_sync(0xffffffffu, l_run[1], off);
    }
    float inv0 = 1.0f / l_run[0], inv1 = 1.0f / l_run[1];

    int srow = s0 + w * 16 + gq;
    size_t m0r = ((size_t)srow * kB + b) * kD + (size_t)h * kDH;
    size_t m1r = ((size_t)(srow + 8) * kB + b) * kD + (size_t)h * kDH;
    #pragma unroll
    for (int nt = 0; nt < 8; nt++) {
        int col = nt * 8 + tg * 2;
        uint32_t hp, lp;
        split_pack(acc_o[nt][0] * inv0, acc_o[nt][1] * inv0, hp, lp);
        *(uint32_t*)(g_oa_hi + m0r + col) = hp;
        *(uint32_t*)(g_oa_lo + m0r + col) = lp;
        split_pack(acc_o[nt][2] * inv1, acc_o[nt][3] * inv1, hp, lp);
        *(uint32_t*)(g_oa_hi + m1r + col) = hp;
        *(uint32_t*)(g_oa_lo + m1r + col) = lp;
    }
}

// ---------------------------------------------------------------------------
extern "C" void kernel_launch(void* const* d_in, const int* in_sizes, int n_in,
                              void* d_out, int out_size) {
    (void)in_sizes; (void)n_in; (void)out_size;
    const float* query = (const float*)d_in[0];
    const float* key   = (const float*)d_in[1];
    const float* value = (const float*)d_in[2];
    const int*   kmask = (const int*)  d_in[3];
    const float* Wq    = (const float*)d_in[4];
    const float* bq    = (const float*)d_in[5];
    const float* Wk    = (const float*)d_in[6];
    const float* bk    = (const float*)d_in[7];
    const float* Wv    = (const float*)d_in[8];
    const float* bvp   = (const float*)d_in[9];
    const float* Wo    = (const float*)d_in[10];
    const float* bo    = (const float*)d_in[11];
    float* out = (float*)d_out;

    cudaFuncSetAttribute(proj_mma_kernel, cudaFuncAttributeMaxDynamicSharedMemorySize, PROJ_SMEM);
    cudaFuncSetAttribute(outproj_mma_kernel, cudaFuncAttributeMaxDynamicSharedMemorySize, GEMM_SMEM);
    cudaFuncSetAttribute(attn_mma_kernel, cudaFuncAttributeMaxDynamicSharedMemorySize, ATTN_SMEM);

    // prep: quantize activations; transpose+quantize qkv weights; wo bf16 split
    quant_act_kernel<<<dim3(kS * kB, 3), 256>>>(query, key, value);
    transpose_wqkv_f32_kernel<<<dim3(kDH / 32, kD / 32, 3 * kH), dim3(32, 8)>>>(Wq, Wk, Wv);
    quant_w_kernel<<<dim3(kH * kDH, 3), 256>>>();
    transpose_wo_kernel<<<dim3(kD / 32, kD / 32), dim3(32, 8)>>>(Wo);

    // int8 projections
    proj_mma_kernel<<<dim3(kS / 128, 3 * kH, kB), 256, PROJ_SMEM>>>(bq, bk, bvp);

    // bf16 attention + output projection
    attn_mma_kernel<<<dim3(kS / 128, kH, kB), 256, ATTN_SMEM>>>(kmask);
    outproj_mma_kernel<<<dim3((kS * kB) / 128, kD / 64), 256, GEMM_SMEM>>>(bo, out);
}

// round 15
// speedup vs baseline: 2.6492x; 2.6492x over previous
#include <cuda_runtime.h>
#include <cuda_bf16.h>
#include <cuda_fp16.h>
#include <math.h>
#include <cstdint>

#define kS  1024
#define kB  4
#define kD  1024
#define kH  16
#define kDH 64

// fp16 single-precision-path scratch (projection + output projection)
__device__ __half g_qa[kS*kB*kD], g_ka[kS*kB*kD], g_va[kS*kB*kD];  // activations
__device__ __half g_wqkv[3][kH*kDH*kD];                            // [which][h*64+n][k]
__device__ __half g_oa[kS*kB*kD];                                  // attn out (concat), fp16
__device__ __half g_wo[kD*kD];                                     // [n][k]

// bf16 split q/k/v for the 3-pass attention kernel (unchanged layout)
__device__ __nv_bfloat16 g_qp_hi[kB*kH*kS*kDH], g_qp_lo[kB*kH*kS*kDH]; // [b][h][s][dh]
__device__ __nv_bfloat16 g_kp_hi[kB*kH*kS*kDH], g_kp_lo[kB*kH*kS*kDH]; // [b][h][s][dh]
__device__ __nv_bfloat16 g_vp_hi[kB*kH*kS*kDH], g_vp_lo[kB*kH*kS*kDH]; // [b][h][dh][s]

// ===================== helpers =====================
__device__ __forceinline__ uint32_t smem_u32(const void* p) {
    uint32_t a;
    asm("{ .reg .u64 t; cvta.to.shared.u64 t, %1; cvt.u32.u64 %0, t; }" : "=r"(a) : "l"(p));
    return a;
}
__device__ __forceinline__ void ldmatrix_x4(uint32_t* r, uint32_t a) {
    asm volatile("ldmatrix.sync.aligned.m8n8.x4.shared.b16 {%0,%1,%2,%3}, [%4];"
        : "=r"(r[0]), "=r"(r[1]), "=r"(r[2]), "=r"(r[3]) : "r"(a));
}
__device__ __forceinline__ void mma_bf16(float* c, const uint32_t* a, const uint32_t* b) {
    asm volatile("mma.sync.aligned.m16n8k16.row.col.f32.bf16.bf16.f32 "
        "{%0,%1,%2,%3},{%4,%5,%6,%7},{%8,%9},{%0,%1,%2,%3};"
        : "+f"(c[0]), "+f"(c[1]), "+f"(c[2]), "+f"(c[3])
        : "r"(a[0]), "r"(a[1]), "r"(a[2]), "r"(a[3]), "r"(b[0]), "r"(b[1]));
}
__device__ __forceinline__ void mma_f16(float* c, const uint32_t* a, const uint32_t* b) {
    asm volatile("mma.sync.aligned.m16n8k16.row.col.f32.f16.f16.f32 "
        "{%0,%1,%2,%3},{%4,%5,%6,%7},{%8,%9},{%0,%1,%2,%3};"
        : "+f"(c[0]), "+f"(c[1]), "+f"(c[2]), "+f"(c[3])
        : "r"(a[0]), "r"(a[1]), "r"(a[2]), "r"(a[3]), "r"(b[0]), "r"(b[1]));
}
__device__ __forceinline__ void split_pack(float x, float y, uint32_t& hp, uint32_t& lp) {
    __nv_bfloat16 hx = __float2bfloat16_rn(x);
    __nv_bfloat16 hy = __float2bfloat16_rn(y);
    __nv_bfloat16 lx = __float2bfloat16_rn(x - __bfloat162float(hx));
    __nv_bfloat16 ly = __float2bfloat16_rn(y - __bfloat162float(hy));
    hp = (uint32_t)__bfloat16_as_ushort(hx) | ((uint32_t)__bfloat16_as_ushort(hy) << 16);
    lp = (uint32_t)__bfloat16_as_ushort(lx) | ((uint32_t)__bfloat16_as_ushort(ly) << 16);
}
__device__ __forceinline__ void cp_async16(uint32_t saddr, const void* gptr) {
    asm volatile("cp.async.cg.shared.global [%0], [%1], 16;" :: "r"(saddr), "l"(gptr));
}
#define CP_COMMIT() asm volatile("cp.async.commit_group;" ::: "memory")
#define CP_WAIT_0() asm volatile("cp.async.wait_group 0;" ::: "memory")

// swizzled offset within a 128B-row tile: row-major, seg XOR (row&7)
__device__ __forceinline__ uint32_t sw_off(int row, int seg) {
    return (uint32_t)(row * 128 + ((seg ^ (row & 7)) << 4));
}

// ===========================================================================
// Prep 1: convert q/k/v activations to fp16. grid (n4/256, 3)
// ===========================================================================
__global__ void __launch_bounds__(256) cvt3_kernel(
    const float* __restrict__ q, const float* __restrict__ k,
    const float* __restrict__ v, int n4)
{
    int which = blockIdx.y;
    const float* src = (which == 0) ? q : (which == 1) ? k : v;
    __half* dst = (which == 0) ? g_qa : (which == 1) ? g_ka : g_va;
    int i = blockIdx.x * blockDim.x + threadIdx.x;
    if (i >= n4) return;
    float4 vv = ((const float4*)src)[i];
    __half2 h0 = __floats2half2_rn(vv.x, vv.y);
    __half2 h1 = __floats2half2_rn(vv.z, vv.w);
    *(uint2*)(dst + (size_t)i * 4) =
        make_uint2(*(uint32_t*)&h0, *(uint32_t*)&h1);
}

// ===========================================================================
// Prep 2: transpose weights to fp16 [n][k]
// ===========================================================================
__global__ void __launch_bounds__(256) transpose_wqkv_kernel(
    const float* __restrict__ Wq, const float* __restrict__ Wk,
    const float* __restrict__ Wv)
{
    __shared__ float tile[32][33];
    int which = blockIdx.z >> 4;
    int h = blockIdx.z & 15;
    const float* src = ((which == 0) ? Wq : (which == 1) ? Wk : Wv) + (size_t)h * kD * kDH;
    __half* dst = g_wqkv[which] + (size_t)h * kDH * kD;
    int c0 = blockIdx.x * 32, r0 = blockIdx.y * 32;
    int tx = threadIdx.x, ty = threadIdx.y;
    #pragma unroll
    for (int i = 0; i < 4; i++)
        tile[ty + i * 8][tx] = src[(size_t)(r0 + ty + i * 8) * kDH + c0 + tx];
    __syncthreads();
    #pragma unroll
    for (int i = 0; i < 4; i++)
        dst[(size_t)(c0 + ty + i * 8) * kD + r0 + tx] = __float2half_rn(tile[tx][ty + i * 8]);
}

__global__ void __launch_bounds__(256) transpose_wo_kernel(const float* __restrict__ Wo)
{
    __shared__ float tile[32][33];
    int c0 = blockIdx.x * 32, r0 = blockIdx.y * 32;
    int tx = threadIdx.x, ty = threadIdx.y;
    #pragma unroll
    for (int i = 0; i < 4; i++)
        tile[ty + i * 8][tx] = Wo[(size_t)(r0 + ty + i * 8) * kD + c0 + tx];
    __syncthreads();
    #pragma unroll
    for (int i = 0; i < 4; i++)
        g_wo[(size_t)(c0 + ty + i * 8) * kD + r0 + tx] = __float2half_rn(tile[tx][ty + i * 8]);
}

// ===========================================================================
// fp16 single-pass GEMM: BM=128, BN=64, BK=64, 256 thr (8 warps 4x2).
// Stage: A 128 rows (16KB) @0, B 64 rows (8KB) @16384; 2 stages = 48KB.
// 1 sync/chunk (wait -> sync -> load(c+1) -> compute(c)).
// ===========================================================================
#define F_A 0
#define F_B 16384
#define F_STG 24576
#define FGEMM_SMEM (2 * F_STG)   // 49152

__device__ __forceinline__ void f16_compute_chunk(
    uint32_t stb, int wm, int wn, int lane, float acc[2][4][4])
{
    int lrow = lane & 15;
    int lseg = lane >> 4;
    #pragma unroll
    for (int ks = 0; ks < 4; ks++) {
        int seg = ks * 2 + lseg;
        uint32_t af[2][4], bf[4][2];
        #pragma unroll
        for (int mt = 0; mt < 2; mt++)
            ldmatrix_x4(af[mt], stb + F_A + sw_off(wm * 32 + mt * 16 + lrow, seg));
        #pragma unroll
        for (int nt2 = 0; nt2 < 2; nt2++) {
            uint32_t t[4];
            ldmatrix_x4(t, stb + F_B + sw_off(wn * 32 + nt2 * 16 + lrow, seg));
            bf[nt2 * 2 + 0][0] = t[0]; bf[nt2 * 2 + 0][1] = t[2];
            bf[nt2 * 2 + 1][0] = t[1]; bf[nt2 * 2 + 1][1] = t[3];
        }
        #pragma unroll
        for (int mt = 0; mt < 2; mt++)
            #pragma unroll
            for (int nt = 0; nt < 4; nt++)
                mma_f16(acc[mt][nt], af[mt], bf[nt]);
    }
}

// ---- fused projections. grid (8, 48, 4): y -> which*16+h ----
__global__ void __launch_bounds__(256, 3) proj_mma_kernel(
    const float* __restrict__ bq, const float* __restrict__ bk,
    const float* __restrict__ bv)
{
    extern __shared__ char smem[];
    uint32_t sbase = smem_u32(smem);
    int s0 = blockIdx.x * 128;
    int which = blockIdx.y >> 4;
    int h  = blockIdx.y & 15;
    int b  = blockIdx.z;
    int tid = threadIdx.x;
    int wid = tid >> 5, lane = tid & 31;
    int wm = wid >> 1, wn = wid & 1;

    const __half* ap = (which == 0) ? g_qa : (which == 1) ? g_ka : g_va;
    const __half* wp = g_wqkv[which];
    const float* bias = (which == 0) ? bq : (which == 1) ? bk : bv;

    float acc[2][4][4];
    #pragma unroll
    for (int mt = 0; mt < 2; mt++)
        #pragma unroll
        for (int nt = 0; nt < 4; nt++)
            #pragma unroll
            for (int e = 0; e < 4; e++) acc[mt][nt][e] = 0.f;

    auto load_chunk = [&](int c, int stg) {
        uint32_t stb = sbase + stg * F_STG;
        int k0 = c * 64;
        #pragma unroll
        for (int i = 0; i < 4; i++) {
            int id = tid + i * 256;        // 0..1023
            int m = id >> 3, k8 = id & 7;
            size_t g = ((size_t)(s0 + m) * kB + b) * kD + k0 + k8 * 8;
            cp_async16(stb + F_A + sw_off(m, k8), ap + g);
        }
        #pragma unroll
        for (int i = 0; i < 2; i++) {
            int id = tid + i * 256;        // 0..511
            int n = id >> 3, k8 = id & 7;
            size_t g = ((size_t)h * kDH + n) * kD + k0 + k8 * 8;
            cp_async16(stb + F_B + sw_off(n, k8), wp + g);
        }
    };

    load_chunk(0, 0);
    CP_COMMIT();
    for (int c = 0; c < 16; c++) {
        CP_WAIT_0();
        __syncthreads();
        if (c + 1 < 16) {
            load_chunk(c + 1, (c + 1) & 1);
            CP_COMMIT();
        }
        f16_compute_chunk(sbase + (c & 1) * F_STG, wm, wn, lane, acc);
    }

    int gq = lane >> 2, tg = lane & 3;
    size_t bh = (size_t)b * kH + h;
    if (which < 2) {
        __nv_bfloat16* oh = (which == 0) ? g_qp_hi : g_kp_hi;
        __nv_bfloat16* ol = (which == 0) ? g_qp_lo : g_kp_lo;
        #pragma unroll
        for (int mt = 0; mt < 2; mt++) {
            int row0 = s0 + wm * 32 + mt * 16 + gq;
            #pragma unroll
            for (int nt = 0; nt < 4; nt++) {
                int col = wn * 32 + nt * 8 + tg * 2;
                float b0 = bias[h * kDH + col], b1 = bias[h * kDH + col + 1];
                uint32_t hpk, lpk;
                size_t off0 = (bh * kS + row0) * kDH + col;
                split_pack(acc[mt][nt][0] + b0, acc[mt][nt][1] + b1, hpk, lpk);
                *(uint32_t*)(oh + off0) = hpk; *(uint32_t*)(ol + off0) = lpk;
                split_pack(acc[mt][nt][2] + b0, acc[mt][nt][3] + b1, hpk, lpk);
                size_t off1 = off0 + (size_t)8 * kDH;
                *(uint32_t*)(oh + off1) = hpk; *(uint32_t*)(ol + off1) = lpk;
            }
        }
    } else {
        // V transposed: [b][h][dh][s]
        #pragma unroll
        for (int mt = 0; mt < 2; mt++) {
            int row0 = s0 + wm * 32 + mt * 16 + gq;
            #pragma unroll
            for (int nt = 0; nt < 4; nt++) {
                int col = wn * 32 + nt * 8 + tg * 2;
                float b0 = bias[h * kDH + col], b1 = bias[h * kDH + col + 1];
                float vals[4] = {acc[mt][nt][0] + b0, acc[mt][nt][1] + b1,
                                 acc[mt][nt][2] + b0, acc[mt][nt][3] + b1};
                int rr[4] = {row0, row0, row0 + 8, row0 + 8};
                int cc[4] = {col, col + 1, col, col + 1};
                #pragma unroll
                for (int e = 0; e < 4; e++) {
                    __nv_bfloat16 hv = __float2bfloat16_rn(vals[e]);
                    __nv_bfloat16 lv = __float2bfloat16_rn(vals[e] - __bfloat162float(hv));
                    size_t off = (bh * kDH + cc[e]) * kS + rr[e];
                    g_vp_hi[off] = hv;
                    g_vp_lo[off] = lv;
                }
            }
        }
    }
}

// ---- output projection, fp16 single-pass. grid (32, 16) ----
__global__ void __launch_bounds__(256, 3) outproj_mma_kernel(
    const float* __restrict__ bo, float* __restrict__ out)
{
    extern __shared__ char smem[];
    uint32_t sbase = smem_u32(smem);
    int m0 = blockIdx.x * 128;
    int n0 = blockIdx.y * 64;
    int tid = threadIdx.x;
    int wid = tid >> 5, lane = tid & 31;
    int wm = wid >> 1, wn = wid & 1;

    float acc[2][4][4];
    #pragma unroll
    for (int mt = 0; mt < 2; mt++)
        #pragma unroll
        for (int nt = 0; nt < 4; nt++)
            #pragma unroll
            for (int e = 0; e < 4; e++) acc[mt][nt][e] = 0.f;

    auto load_chunk = [&](int c, int stg) {
        uint32_t stb = sbase + stg * F_STG;
        int k0 = c * 64;
        #pragma unroll
        for (int i = 0; i < 4; i++) {
            int id = tid + i * 256;
            int m = id >> 3, k8 = id & 7;
            size_t g = (size_t)(m0 + m) * kD + k0 + k8 * 8;
            cp_async16(stb + F_A + sw_off(m, k8), g_oa + g);
        }
        #pragma unroll
        for (int i = 0; i < 2; i++) {
            int id = tid + i * 256;
            int n = id >> 3, k8 = id & 7;
            size_t g = (size_t)(n0 + n) * kD + k0 + k8 * 8;
            cp_async16(stb + F_B + sw_off(n, k8), g_wo + g);
        }
    };

    load_chunk(0, 0);
    CP_COMMIT();
    for (int c = 0; c < 16; c++) {
        CP_WAIT_0();
        __syncthreads();
        if (c + 1 < 16) {
            load_chunk(c + 1, (c + 1) & 1);
            CP_COMMIT();
        }
        f16_compute_chunk(sbase + (c & 1) * F_STG, wm, wn, lane, acc);
    }

    int gq = lane >> 2, tg = lane & 3;
    #pragma unroll
    for (int mt = 0; mt < 2; mt++) {
        int row = m0 + wm * 32 + mt * 16 + gq;
        #pragma unroll
        for (int nt = 0; nt < 4; nt++) {
            int col = n0 + wn * 32 + nt * 8 + tg * 2;
            float b0 = bo[col], b1 = bo[col + 1];
            size_t r0 = (size_t)row * kD + col;
            *(float2*)(out + r0) = make_float2(acc[mt][nt][0] + b0, acc[mt][nt][1] + b1);
            *(float2*)(out + r0 + 8 * kD) = make_float2(acc[mt][nt][2] + b0, acc[mt][nt][3] + b1);
        }
    }
}

// ===========================================================================
// Tensor-core attention — round-12 proven version (bf16 3-pass, 2-stage,
// 1 sync/tile). Epilogue now writes fp16 g_oa for the fp16 outproj.
// ===========================================================================
#define AK_HI 0
#define AK_LO 8192
#define AV_HI 16384
#define AV_LO 24576
#define ASTG  32768
#define AMK   65536
#define ATTN_SMEM (65536 + 4096)

__global__ void __launch_bounds__(256) attn_mma_kernel(const int* __restrict__ mask)
{
    extern __shared__ char smem[];
    uint32_t sbase = smem_u32(smem);
    int s0 = blockIdx.x * 128;
    int h  = blockIdx.y;
    int b  = blockIdx.z;
    int tid = threadIdx.x;
    int w = tid >> 5, lane = tid & 31;
    int gq = lane >> 2, tg = lane & 3;
    size_t bh = (size_t)b * kH + h;

    const __nv_bfloat16* qh = g_qp_hi + bh * kS * kDH;
    const __nv_bfloat16* ql = g_qp_lo + bh * kS * kDH;
    const __nv_bfloat16* kh = g_kp_hi + bh * kS * kDH;
    const __nv_bfloat16* kl = g_kp_lo + bh * kS * kDH;
    const __nv_bfloat16* vth = g_vp_hi + bh * kDH * kS;  // [dh][s]
    const __nv_bfloat16* vtl = g_vp_lo + bh * kDH * kS;

    float* Mk = (float*)(smem + AMK);
    for (int idx = tid; idx < kS; idx += 256)
        Mk[idx] = (float)mask[(size_t)idx * kB + b] * 1e18f;

    #pragma unroll
    for (int i = 0; i < 4; i++) {
        int id = tid + i * 256;
        int row = id >> 3, k8 = id & 7;
        size_t g = (size_t)(s0 + row) * kDH + k8 * 8;
        uint32_t d = sbase + sw_off(row, k8);
        cp_async16(d, qh + g);
        cp_async16(d + 16384, ql + g);
    }
    CP_COMMIT();
    CP_WAIT_0();
    __syncthreads();
    uint32_t qfh[4][4], qfl[4][4];
    int lrow = lane & 15, lseg = lane >> 4;
    #pragma unroll
    for (int ks = 0; ks < 4; ks++) {
        uint32_t addr = sbase + sw_off(w * 16 + lrow, ks * 2 + lseg);
        ldmatrix_x4(qfh[ks], addr);
        ldmatrix_x4(qfl[ks], addr + 16384);
    }
    __syncthreads();  // Q reads done before stage reuse

    float acc_o[8][4];
    #pragma unroll
    for (int nt = 0; nt < 8; nt++)
        #pragma unroll
        for (int e = 0; e < 4; e++) acc_o[nt][e] = 0.f;
    float l_run[2] = {0.f, 0.f};
    const float scale = 0.125f;

    auto load_tile = [&](int t, int stg) {
        uint32_t stb = sbase + stg * ASTG;
        int j0 = t * 64;
        #pragma unroll
        for (int i = 0; i < 8; i++) {
            int id = tid + (i & 1) * 256;
            int row = id >> 3, k8 = id & 7;
            const __nv_bfloat16* src;
            uint32_t dst;
            if (i < 2)      { src = kh  + (size_t)(j0 + row) * kDH + k8 * 8; dst = AK_HI; }
            else if (i < 4) { src = kl  + (size_t)(j0 + row) * kDH + k8 * 8; dst = AK_LO; }
            else if (i < 6) { src = vth + (size_t)row * kS + j0 + k8 * 8;    dst = AV_HI; }
            else            { src = vtl + (size_t)row * kS + j0 + k8 * 8;    dst = AV_LO; }
            cp_async16(stb + dst + sw_off(row, k8), src);
        }
    };

    load_tile(0, 0);
    CP_COMMIT();
    for (int t = 0; t < 16; t++) {
        CP_WAIT_0();
        __syncthreads();
        if (t + 1 < 16) {
            load_tile(t + 1, (t + 1) & 1);
            CP_COMMIT();
        }
        uint32_t stb = sbase + (t & 1) * ASTG;
        int j0 = t * 64;

        // ---- S = Q K^T (3-pass) ----
        float ps[8][4];
        #pragma unroll
        for (int nt = 0; nt < 8; nt++)
            #pragma unroll
            for (int e = 0; e < 4; e++) ps[nt][e] = 0.f;
        #pragma unroll
        for (int ks = 0; ks < 4; ks++) {
            int seg = ks * 2 + lseg;
            #pragma unroll
            for (int nt2 = 0; nt2 < 4; nt2++) {
                uint32_t addr = stb + AK_HI + sw_off(nt2 * 16 + lrow, seg);
                uint32_t tt[4], u[4];
                ldmatrix_x4(tt, addr);
                ldmatrix_x4(u, addr + (AK_LO - AK_HI));
                uint32_t bh0[2] = {tt[0], tt[2]}, bh1[2] = {tt[1], tt[3]};
                uint32_t bl0[2] = {u[0], u[2]}, bl1[2] = {u[1], u[3]};
                mma_bf16(ps[nt2 * 2 + 0], qfh[ks], bh0);
                mma_bf16(ps[nt2 * 2 + 0], qfh[ks], bl0);
                mma_bf16(ps[nt2 * 2 + 0], qfl[ks], bh0);
                mma_bf16(ps[nt2 * 2 + 1], qfh[ks], bh1);
                mma_bf16(ps[nt2 * 2 + 1], qfh[ks], bl1);
                mma_bf16(ps[nt2 * 2 + 1], qfl[ks], bh1);
            }
        }

        // ---- softmax weights ----
        float l0 = 0.f, l1 = 0.f;
        #pragma unroll
        for (int nt = 0; nt < 8; nt++) {
            float mk0 = Mk[j0 + nt * 8 + tg * 2], mk1 = Mk[j0 + nt * 8 + tg * 2 + 1];
            float p0 = __expf(fminf(ps[nt][0] * scale - mk0, 60.f));
            float p1 = __expf(fminf(ps[nt][1] * scale - mk1, 60.f));
            float p2 = __expf(fminf(ps[nt][2] * scale - mk0, 60.f));
            float p3 = __expf(fminf(ps[nt][3] * scale - mk1, 60.f));
            l0 += p0 + p1; l1 += p2 + p3;
            ps[nt][0] = p0; ps[nt][1] = p1; ps[nt][2] = p2; ps[nt][3] = p3;
        }
        l_run[0] += l0; l_run[1] += l1;

        // ---- O += P V (P split in regs, 3-pass) ----
        #pragma unroll
        for (int ks = 0; ks < 4; ks++) {
            uint32_t pah[4], pal[4];
            split_pack(ps[2 * ks + 0][0], ps[2 * ks + 0][1], pah[0], pal[0]);
            split_pack(ps[2 * ks + 0][2], ps[2 * ks + 0][3], pah[1], pal[1]);
            split_pack(ps[2 * ks + 1][0], ps[2 * ks + 1][1], pah[2], pal[2]);
            split_pack(ps[2 * ks + 1][2], ps[2 * ks + 1][3], pah[3], pal[3]);
            int seg = ks * 2 + lseg;
            #pragma unroll
            for (int nd2 = 0; nd2 < 4; nd2++) {
                uint32_t addr = stb + AV_HI + sw_off(nd2 * 16 + lrow, seg);
                uint32_t tt[4], u[4];
                ldmatrix_x4(tt, addr);
                ldmatrix_x4(u, addr + (AV_LO - AV_HI));
                uint32_t bh0[2] = {tt[0], tt[2]}, bh1[2] = {tt[1], tt[3]};
                uint32_t bl0[2] = {u[0], u[2]}, bl1[2] = {u[1], u[3]};
                mma_bf16(acc_o[nd2 * 2 + 0], pah, bh0);
                mma_bf16(acc_o[nd2 * 2 + 0], pah, bl0);
                mma_bf16(acc_o[nd2 * 2 + 0], pal, bh0);
                mma_bf16(acc_o[nd2 * 2 + 1], pah, bh1);
                mma_bf16(acc_o[nd2 * 2 + 1], pah, bl1);
                mma_bf16(acc_o[nd2 * 2 + 1], pal, bh1);
            }
        }
    }

    // ---- normalize and write fp16 concat output ----
    #pragma unroll
    for (int off = 1; off <= 2; off <<= 1) {
        l_run[0] += __shfl_xor_sync(0xffffffffu, l_run[0], off);
        l_run[1] += __shfl_xor_sync(0xffffffffu, l_run[1], off);
    }
    float inv0 = 1.0f / l_run[0], inv1 = 1.0f / l_run[1];

    int srow = s0 + w * 16 + gq;
    size_t m0r = ((size_t)srow * kB + b) * kD + (size_t)h * kDH;
    size_t m1r = ((size_t)(srow + 8) * kB + b) * kD + (size_t)h * kDH;
    #pragma unroll
    for (int nt = 0; nt < 8; nt++) {
        int col = nt * 8 + tg * 2;
        __half2 o0 = __floats2half2_rn(acc_o[nt][0] * inv0, acc_o[nt][1] * inv0);
        __half2 o1 = __floats2half2_rn(acc_o[nt][2] * inv1, acc_o[nt][3] * inv1);
        *(uint32_t*)(g_oa + m0r + col) = *(uint32_t*)&o0;
        *(uint32_t*)(g_oa + m1r + col) = *(uint32_t*)&o1;
    }
}

// ---------------------------------------------------------------------------
extern "C" void kernel_launch(void* const* d_in, const int* in_sizes, int n_in,
                              void* d_out, int out_size) {
    (void)in_sizes; (void)n_in; (void)out_size;
    const float* query = (const float*)d_in[0];
    const float* key   = (const float*)d_in[1];
    const float* value = (const float*)d_in[2];
    const int*   kmask = (const int*)  d_in[3];
    const float* Wq    = (const float*)d_in[4];
    const float* bq    = (const float*)d_in[5];
    const float* Wk    = (const float*)d_in[6];
    const float* bk    = (const float*)d_in[7];
    const float* Wv    = (const float*)d_in[8];
    const float* bvp   = (const float*)d_in[9];
    const float* Wo    = (const float*)d_in[10];
    const float* bo    = (const float*)d_in[11];
    float* out = (float*)d_out;

    cudaFuncSetAttribute(proj_mma_kernel, cudaFuncAttributeMaxDynamicSharedMemorySize, FGEMM_SMEM);
    cudaFuncSetAttribute(outproj_mma_kernel, cudaFuncAttributeMaxDynamicSharedMemorySize, FGEMM_SMEM);
    cudaFuncSetAttribute(attn_mma_kernel, cudaFuncAttributeMaxDynamicSharedMemorySize, ATTN_SMEM);

    const int n4_act = kS * kB * kD / 4;

    cvt3_kernel<<<dim3(n4_act / 256, 3), 256>>>(query, key, value, n4_act);
    transpose_wqkv_kernel<<<dim3(kDH / 32, kD / 32, 3 * kH), dim3(32, 8)>>>(Wq, Wk, Wv);
    transpose_wo_kernel<<<dim3(kD / 32, kD / 32), dim3(32, 8)>>>(Wo);

    proj_mma_kernel<<<dim3(kS / 128, 3 * kH, kB), 256, FGEMM_SMEM>>>(bq, bk, bvp);

    attn_mma_kernel<<<dim3(kS / 128, kH, kB), 256, ATTN_SMEM>>>(kmask);

    outproj_mma_kernel<<<dim3((kS * kB) / 128, kD / 64), 256, FGEMM_SMEM>>>(bo, out);
}

// round 16
// speedup vs baseline: 4.0299x; 1.5211x over previous
#include <cuda_runtime.h>
#include <cuda_fp16.h>
#include <math.h>
#include <cstdint>

#define kS  1024
#define kB  4
#define kD  1024
#define kH  16
#define kDH 64

// fp16 scratch
__device__ __half g_qa[kS*kB*kD], g_ka[kS*kB*kD], g_va[kS*kB*kD];  // activations
__device__ __half g_wqkv[3][kH*kDH*kD];                            // [which][h*64+n][k]
__device__ __half g_oa[kS*kB*kD];                                  // attn out (concat)
__device__ __half g_wo[kD*kD];                                     // [n][k]
__device__ __half g_qp[kB*kH*kS*kDH];                              // [b][h][s][dh]
__device__ __half g_kp[kB*kH*kS*kDH];                              // [b][h][s][dh]
__device__ __half g_vp[kB*kH*kS*kDH];                              // [b][h][dh][s]

// ===================== helpers =====================
__device__ __forceinline__ uint32_t smem_u32(const void* p) {
    uint32_t a;
    asm("{ .reg .u64 t; cvta.to.shared.u64 t, %1; cvt.u32.u64 %0, t; }" : "=r"(a) : "l"(p));
    return a;
}
__device__ __forceinline__ void ldmatrix_x4(uint32_t* r, uint32_t a) {
    asm volatile("ldmatrix.sync.aligned.m8n8.x4.shared.b16 {%0,%1,%2,%3}, [%4];"
        : "=r"(r[0]), "=r"(r[1]), "=r"(r[2]), "=r"(r[3]) : "r"(a));
}
__device__ __forceinline__ void mma_f16(float* c, const uint32_t* a, const uint32_t* b) {
    asm volatile("mma.sync.aligned.m16n8k16.row.col.f32.f16.f16.f32 "
        "{%0,%1,%2,%3},{%4,%5,%6,%7},{%8,%9},{%0,%1,%2,%3};"
        : "+f"(c[0]), "+f"(c[1]), "+f"(c[2]), "+f"(c[3])
        : "r"(a[0]), "r"(a[1]), "r"(a[2]), "r"(a[3]), "r"(b[0]), "r"(b[1]));
}
__device__ __forceinline__ uint32_t pack_h2(float x, float y) {
    __half2 h = __floats2half2_rn(x, y);
    return *(uint32_t*)&h;
}
__device__ __forceinline__ void cp_async16(uint32_t saddr, const void* gptr) {
    asm volatile("cp.async.cg.shared.global [%0], [%1], 16;" :: "r"(saddr), "l"(gptr));
}
#define CP_COMMIT() asm volatile("cp.async.commit_group;" ::: "memory")
#define CP_WAIT_0() asm volatile("cp.async.wait_group 0;" ::: "memory")

// swizzled offset within a 128B-row tile: row-major, seg XOR (row&7)
__device__ __forceinline__ uint32_t sw_off(int row, int seg) {
    return (uint32_t)(row * 128 + ((seg ^ (row & 7)) << 4));
}

// ===========================================================================
// Prep 1: convert q/k/v activations to fp16. grid (n4/256, 3)
// ===========================================================================
__global__ void __launch_bounds__(256) cvt3_kernel(
    const float* __restrict__ q, const float* __restrict__ k,
    const float* __restrict__ v, int n4)
{
    int which = blockIdx.y;
    const float* src = (which == 0) ? q : (which == 1) ? k : v;
    __half* dst = (which == 0) ? g_qa : (which == 1) ? g_ka : g_va;
    int i = blockIdx.x * blockDim.x + threadIdx.x;
    if (i >= n4) return;
    float4 vv = ((const float4*)src)[i];
    *(uint2*)(dst + (size_t)i * 4) =
        make_uint2(pack_h2(vv.x, vv.y), pack_h2(vv.z, vv.w));
}

// ===========================================================================
// Prep 2: transpose weights to fp16 [n][k]
// ===========================================================================
__global__ void __launch_bounds__(256) transpose_wqkv_kernel(
    const float* __restrict__ Wq, const float* __restrict__ Wk,
    const float* __restrict__ Wv)
{
    __shared__ float tile[32][33];
    int which = blockIdx.z >> 4;
    int h = blockIdx.z & 15;
    const float* src = ((which == 0) ? Wq : (which == 1) ? Wk : Wv) + (size_t)h * kD * kDH;
    __half* dst = g_wqkv[which] + (size_t)h * kDH * kD;
    int c0 = blockIdx.x * 32, r0 = blockIdx.y * 32;
    int tx = threadIdx.x, ty = threadIdx.y;
    #pragma unroll
    for (int i = 0; i < 4; i++)
        tile[ty + i * 8][tx] = src[(size_t)(r0 + ty + i * 8) * kDH + c0 + tx];
    __syncthreads();
    #pragma unroll
    for (int i = 0; i < 4; i++)
        dst[(size_t)(c0 + ty + i * 8) * kD + r0 + tx] = __float2half_rn(tile[tx][ty + i * 8]);
}

__global__ void __launch_bounds__(256) transpose_wo_kernel(const float* __restrict__ Wo)
{
    __shared__ float tile[32][33];
    int c0 = blockIdx.x * 32, r0 = blockIdx.y * 32;
    int tx = threadIdx.x, ty = threadIdx.y;
    #pragma unroll
    for (int i = 0; i < 4; i++)
        tile[ty + i * 8][tx] = Wo[(size_t)(r0 + ty + i * 8) * kD + c0 + tx];
    __syncthreads();
    #pragma unroll
    for (int i = 0; i < 4; i++)
        g_wo[(size_t)(c0 + ty + i * 8) * kD + r0 + tx] = __float2half_rn(tile[tx][ty + i * 8]);
}

// ===========================================================================
// fp16 single-pass GEMM: BM=128, BN=64, BK=64, 256 thr (8 warps 4x2).
// Stage: A 128 rows (16KB) @0, B 64 rows (8KB) @16384; 2 stages = 48KB.
// ===========================================================================
#define F_A 0
#define F_B 16384
#define F_STG 24576
#define FGEMM_SMEM (2 * F_STG)   // 49152

__device__ __forceinline__ void f16_compute_chunk(
    uint32_t stb, int wm, int wn, int lane, float acc[2][4][4])
{
    int lrow = lane & 15;
    int lseg = lane >> 4;
    #pragma unroll
    for (int ks = 0; ks < 4; ks++) {
        int seg = ks * 2 + lseg;
        uint32_t af[2][4], bf[4][2];
        #pragma unroll
        for (int mt = 0; mt < 2; mt++)
            ldmatrix_x4(af[mt], stb + F_A + sw_off(wm * 32 + mt * 16 + lrow, seg));
        #pragma unroll
        for (int nt2 = 0; nt2 < 2; nt2++) {
            uint32_t t[4];
            ldmatrix_x4(t, stb + F_B + sw_off(wn * 32 + nt2 * 16 + lrow, seg));
            bf[nt2 * 2 + 0][0] = t[0]; bf[nt2 * 2 + 0][1] = t[2];
            bf[nt2 * 2 + 1][0] = t[1]; bf[nt2 * 2 + 1][1] = t[3];
        }
        #pragma unroll
        for (int mt = 0; mt < 2; mt++)
            #pragma unroll
            for (int nt = 0; nt < 4; nt++)
                mma_f16(acc[mt][nt], af[mt], bf[nt]);
    }
}

// ---- fused projections. grid (8, 48, 4): y -> which*16+h ----
__global__ void __launch_bounds__(256, 3) proj_mma_kernel(
    const float* __restrict__ bq, const float* __restrict__ bk,
    const float* __restrict__ bv)
{
    extern __shared__ char smem[];
    uint32_t sbase = smem_u32(smem);
    int s0 = blockIdx.x * 128;
    int which = blockIdx.y >> 4;
    int h  = blockIdx.y & 15;
    int b  = blockIdx.z;
    int tid = threadIdx.x;
    int wid = tid >> 5, lane = tid & 31;
    int wm = wid >> 1, wn = wid & 1;

    const __half* ap = (which == 0) ? g_qa : (which == 1) ? g_ka : g_va;
    const __half* wp = g_wqkv[which];
    const float* bias = (which == 0) ? bq : (which == 1) ? bk : bv;

    float acc[2][4][4];
    #pragma unroll
    for (int mt = 0; mt < 2; mt++)
        #pragma unroll
        for (int nt = 0; nt < 4; nt++)
            #pragma unroll
            for (int e = 0; e < 4; e++) acc[mt][nt][e] = 0.f;

    auto load_chunk = [&](int c, int stg) {
        uint32_t stb = sbase + stg * F_STG;
        int k0 = c * 64;
        #pragma unroll
        for (int i = 0; i < 4; i++) {
            int id = tid + i * 256;
            int m = id >> 3, k8 = id & 7;
            size_t g = ((size_t)(s0 + m) * kB + b) * kD + k0 + k8 * 8;
            cp_async16(stb + F_A + sw_off(m, k8), ap + g);
        }
        #pragma unroll
        for (int i = 0; i < 2; i++) {
            int id = tid + i * 256;
            int n = id >> 3, k8 = id & 7;
            size_t g = ((size_t)h * kDH + n) * kD + k0 + k8 * 8;
            cp_async16(stb + F_B + sw_off(n, k8), wp + g);
        }
    };

    load_chunk(0, 0);
    CP_COMMIT();
    for (int c = 0; c < 16; c++) {
        CP_WAIT_0();
        __syncthreads();
        if (c + 1 < 16) {
            load_chunk(c + 1, (c + 1) & 1);
            CP_COMMIT();
        }
        f16_compute_chunk(sbase + (c & 1) * F_STG, wm, wn, lane, acc);
    }

    int gq = lane >> 2, tg = lane & 3;
    size_t bh = (size_t)b * kH + h;
    if (which < 2) {
        __half* op = (which == 0) ? g_qp : g_kp;
        #pragma unroll
        for (int mt = 0; mt < 2; mt++) {
            int row0 = s0 + wm * 32 + mt * 16 + gq;
            #pragma unroll
            for (int nt = 0; nt < 4; nt++) {
                int col = wn * 32 + nt * 8 + tg * 2;
                float b0 = bias[h * kDH + col], b1 = bias[h * kDH + col + 1];
                size_t off0 = (bh * kS + row0) * kDH + col;
                *(uint32_t*)(op + off0) = pack_h2(acc[mt][nt][0] + b0, acc[mt][nt][1] + b1);
                *(uint32_t*)(op + off0 + (size_t)8 * kDH) =
                    pack_h2(acc[mt][nt][2] + b0, acc[mt][nt][3] + b1);
            }
        }
    } else {
        // V transposed: [b][h][dh][s]
        #pragma unroll
        for (int mt = 0; mt < 2; mt++) {
            int row0 = s0 + wm * 32 + mt * 16 + gq;
            #pragma unroll
            for (int nt = 0; nt < 4; nt++) {
                int col = wn * 32 + nt * 8 + tg * 2;
                float b0 = bias[h * kDH + col], b1 = bias[h * kDH + col + 1];
                float vals[4] = {acc[mt][nt][0] + b0, acc[mt][nt][1] + b1,
                                 acc[mt][nt][2] + b0, acc[mt][nt][3] + b1};
                int rr[4] = {row0, row0, row0 + 8, row0 + 8};
                int cc[4] = {col, col + 1, col, col + 1};
                #pragma unroll
                for (int e = 0; e < 4; e++)
                    g_vp[(bh * kDH + cc[e]) * kS + rr[e]] = __float2half_rn(vals[e]);
            }
        }
    }
}

// ---- output projection, fp16 single-pass. grid (32, 16) ----
__global__ void __launch_bounds__(256, 3) outproj_mma_kernel(
    const float* __restrict__ bo, float* __restrict__ out)
{
    extern __shared__ char smem[];
    uint32_t sbase = smem_u32(smem);
    int m0 = blockIdx.x * 128;
    int n0 = blockIdx.y * 64;
    int tid = threadIdx.x;
    int wid = tid >> 5, lane = tid & 31;
    int wm = wid >> 1, wn = wid & 1;

    float acc[2][4][4];
    #pragma unroll
    for (int mt = 0; mt < 2; mt++)
        #pragma unroll
        for (int nt = 0; nt < 4; nt++)
            #pragma unroll
            for (int e = 0; e < 4; e++) acc[mt][nt][e] = 0.f;

    auto load_chunk = [&](int c, int stg) {
        uint32_t stb = sbase + stg * F_STG;
        int k0 = c * 64;
        #pragma unroll
        for (int i = 0; i < 4; i++) {
            int id = tid + i * 256;
            int m = id >> 3, k8 = id & 7;
            size_t g = (size_t)(m0 + m) * kD + k0 + k8 * 8;
            cp_async16(stb + F_A + sw_off(m, k8), g_oa + g);
        }
        #pragma unroll
        for (int i = 0; i < 2; i++) {
            int id = tid + i * 256;
            int n = id >> 3, k8 = id & 7;
            size_t g = (size_t)(n0 + n) * kD + k0 + k8 * 8;
            cp_async16(stb + F_B + sw_off(n, k8), g_wo + g);
        }
    };

    load_chunk(0, 0);
    CP_COMMIT();
    for (int c = 0; c < 16; c++) {
        CP_WAIT_0();
        __syncthreads();
        if (c + 1 < 16) {
            load_chunk(c + 1, (c + 1) & 1);
            CP_COMMIT();
        }
        f16_compute_chunk(sbase + (c & 1) * F_STG, wm, wn, lane, acc);
    }

    int gq = lane >> 2, tg = lane & 3;
    #pragma unroll
    for (int mt = 0; mt < 2; mt++) {
        int row = m0 + wm * 32 + mt * 16 + gq;
        #pragma unroll
        for (int nt = 0; nt < 4; nt++) {
            int col = n0 + wn * 32 + nt * 8 + tg * 2;
            float b0 = bo[col], b1 = bo[col + 1];
            size_t r0 = (size_t)row * kD + col;
            *(float2*)(out + r0) = make_float2(acc[mt][nt][0] + b0, acc[mt][nt][1] + b1);
            *(float2*)(out + r0 + 8 * kD) = make_float2(acc[mt][nt][2] + b0, acc[mt][nt][3] + b1);
        }
    }
}

// ===========================================================================
// fp16 single-pass attention. Per (b,h): 128 q-rows/CTA, 8 warps x 16 rows.
// Stage (16KB): K 64x128B @0, Vt 64x128B @8192. 2 stages = 32KB; mask 4KB.
// Loop: wait -> sync -> load(t+1) -> compute(t). Q staged once in stage 0/1.
// ===========================================================================
#define A_K 0
#define A_V 8192
#define ASTG 16384
#define AMK  32768
#define ATTN_SMEM (32768 + 4096)

__global__ void __launch_bounds__(256) attn_mma_kernel(const int* __restrict__ mask)
{
    extern __shared__ char smem[];
    uint32_t sbase = smem_u32(smem);
    int s0 = blockIdx.x * 128;
    int h  = blockIdx.y;
    int b  = blockIdx.z;
    int tid = threadIdx.x;
    int w = tid >> 5, lane = tid & 31;
    int gq = lane >> 2, tg = lane & 3;
    size_t bh = (size_t)b * kH + h;

    const __half* qp = g_qp + bh * kS * kDH;
    const __half* kp = g_kp + bh * kS * kDH;
    const __half* vt = g_vp + bh * kDH * kS;   // [dh][s]

    // ---- mask preload ----
    float* Mk = (float*)(smem + AMK);
    for (int idx = tid; idx < kS; idx += 256)
        Mk[idx] = (float)mask[(size_t)idx * kB + b] * 1e18f;

    // ---- stage Q tile (128 rows x 128B, spans both stages) ----
    #pragma unroll
    for (int i = 0; i < 4; i++) {
        int id = tid + i * 256;
        int row = id >> 3, k8 = id & 7;
        size_t g = (size_t)(s0 + row) * kDH + k8 * 8;
        cp_async16(sbase + sw_off(row, k8), qp + g);
    }
    CP_COMMIT();
    CP_WAIT_0();
    __syncthreads();
    uint32_t qf[4][4];
    int lrow = lane & 15, lseg = lane >> 4;
    #pragma unroll
    for (int ks = 0; ks < 4; ks++)
        ldmatrix_x4(qf[ks], sbase + sw_off(w * 16 + lrow, ks * 2 + lseg));
    __syncthreads();  // Q reads done before stage reuse

    float acc_o[8][4];
    #pragma unroll
    for (int nt = 0; nt < 8; nt++)
        #pragma unroll
        for (int e = 0; e < 4; e++) acc_o[nt][e] = 0.f;
    float l_run[2] = {0.f, 0.f};
    const float scale = 0.125f;

    auto load_tile = [&](int t, int stg) {
        uint32_t stb = sbase + stg * ASTG;
        int j0 = t * 64;
        #pragma unroll
        for (int i = 0; i < 4; i++) {
            int id = tid + (i & 1) * 256;
            int row = id >> 3, k8 = id & 7;
            if (i < 2)
                cp_async16(stb + A_K + sw_off(row, k8),
                           kp + (size_t)(j0 + row) * kDH + k8 * 8);
            else
                cp_async16(stb + A_V + sw_off(row, k8),
                           vt + (size_t)row * kS + j0 + k8 * 8);
        }
    };

    load_tile(0, 0);
    CP_COMMIT();
    for (int t = 0; t < 16; t++) {
        CP_WAIT_0();
        __syncthreads();
        if (t + 1 < 16) {
            load_tile(t + 1, (t + 1) & 1);
            CP_COMMIT();
        }
        uint32_t stb = sbase + (t & 1) * ASTG;
        int j0 = t * 64;

        // ---- S = Q K^T ----
        float ps[8][4];
        #pragma unroll
        for (int nt = 0; nt < 8; nt++)
            #pragma unroll
            for (int e = 0; e < 4; e++) ps[nt][e] = 0.f;
        #pragma unroll
        for (int ks = 0; ks < 4; ks++) {
            int seg = ks * 2 + lseg;
            #pragma unroll
            for (int nt2 = 0; nt2 < 4; nt2++) {
                uint32_t t4[4];
                ldmatrix_x4(t4, stb + A_K + sw_off(nt2 * 16 + lrow, seg));
                uint32_t b0[2] = {t4[0], t4[2]}, b1[2] = {t4[1], t4[3]};
                mma_f16(ps[nt2 * 2 + 0], qf[ks], b0);
                mma_f16(ps[nt2 * 2 + 1], qf[ks], b1);
            }
        }

        // ---- softmax weights (no running max; masked -> exactly 0) ----
        float l0 = 0.f, l1 = 0.f;
        #pragma unroll
        for (int nt = 0; nt < 8; nt++) {
            float mk0 = Mk[j0 + nt * 8 + tg * 2], mk1 = Mk[j0 + nt * 8 + tg * 2 + 1];
            float p0 = __expf(fminf(ps[nt][0] * scale - mk0, 60.f));
            float p1 = __expf(fminf(ps[nt][1] * scale - mk1, 60.f));
            float p2 = __expf(fminf(ps[nt][2] * scale - mk0, 60.f));
            float p3 = __expf(fminf(ps[nt][3] * scale - mk1, 60.f));
            l0 += p0 + p1; l1 += p2 + p3;
            ps[nt][0] = p0; ps[nt][1] = p1; ps[nt][2] = p2; ps[nt][3] = p3;
        }
        l_run[0] += l0; l_run[1] += l1;

        // ---- O += P V (P packed to fp16 in regs) ----
        #pragma unroll
        for (int ks = 0; ks < 4; ks++) {
            uint32_t pa[4];
            pa[0] = pack_h2(ps[2 * ks + 0][0], ps[2 * ks + 0][1]);
            pa[1] = pack_h2(ps[2 * ks + 0][2], ps[2 * ks + 0][3]);
            pa[2] = pack_h2(ps[2 * ks + 1][0], ps[2 * ks + 1][1]);
            pa[3] = pack_h2(ps[2 * ks + 1][2], ps[2 * ks + 1][3]);
            int seg = ks * 2 + lseg;
            #pragma unroll
            for (int nd2 = 0; nd2 < 4; nd2++) {
                uint32_t t4[4];
                ldmatrix_x4(t4, stb + A_V + sw_off(nd2 * 16 + lrow, seg));
                uint32_t b0[2] = {t4[0], t4[2]}, b1[2] = {t4[1], t4[3]};
                mma_f16(acc_o[nd2 * 2 + 0], pa, b0);
                mma_f16(acc_o[nd2 * 2 + 1], pa, b1);
            }
        }
    }

    // ---- normalize and write fp16 concat output ----
    #pragma unroll
    for (int off = 1; off <= 2; off <<= 1) {
        l_run[0] += __shfl_xor_sync(0xffffffffu, l_run[0], off);
        l_run[1] += __shfl_xor_sync(0xffffffffu, l_run[1], off);
    }
    float inv0 = 1.0f / l_run[0], inv1 = 1.0f / l_run[1];

    int srow = s0 + w * 16 + gq;
    size_t m0r = ((size_t)srow * kB + b) * kD + (size_t)h * kDH;
    size_t m1r = ((size_t)(srow + 8) * kB + b) * kD + (size_t)h * kDH;
    #pragma unroll
    for (int nt = 0; nt < 8; nt++) {
        int col = nt * 8 + tg * 2;
        *(uint32_t*)(g_oa + m0r + col) = pack_h2(acc_o[nt][0] * inv0, acc_o[nt][1] * inv0);
        *(uint32_t*)(g_oa + m1r + col) = pack_h2(acc_o[nt][2] * inv1, acc_o[nt][3] * inv1);
    }
}

// ---------------------------------------------------------------------------
extern "C" void kernel_launch(void* const* d_in, const int* in_sizes, int n_in,
                              void* d_out, int out_size) {
    (void)in_sizes; (void)n_in; (void)out_size;
    const float* query = (const float*)d_in[0];
    const float* key   = (const float*)d_in[1];
    const float* value = (const float*)d_in[2];
    const int*   kmask = (const int*)  d_in[3];
    const float* Wq    = (const float*)d_in[4];
    const float* bq    = (const float*)d_in[5];
    const float* Wk    = (const float*)d_in[6];
    const float* bk    = (const float*)d_in[7];
    const float* Wv    = (const float*)d_in[8];
    const float* bvp   = (const float*)d_in[9];
    const float* Wo    = (const float*)d_in[10];
    const float* bo    = (const float*)d_in[11];
    float* out = (float*)d_out;

    cudaFuncSetAttribute(proj_mma_kernel, cudaFuncAttributeMaxDynamicSharedMemorySize, FGEMM_SMEM);
    cudaFuncSetAttribute(outproj_mma_kernel, cudaFuncAttributeMaxDynamicSharedMemorySize, FGEMM_SMEM);
    cudaFuncSetAttribute(attn_mma_kernel, cudaFuncAttributeMaxDynamicSharedMemorySize, ATTN_SMEM);

    const int n4_act = kS * kB * kD / 4;

    cvt3_kernel<<<dim3(n4_act / 256, 3), 256>>>(query, key, value, n4_act);
    transpose_wqkv_kernel<<<dim3(kDH / 32, kD / 32, 3 * kH), dim3(32, 8)>>>(Wq, Wk, Wv);
    transpose_wo_kernel<<<dim3(kD / 32, kD / 32), dim3(32, 8)>>>(Wo);

    proj_mma_kernel<<<dim3(kS / 128, 3 * kH, kB), 256, FGEMM_SMEM>>>(bq, bk, bvp);

    attn_mma_kernel<<<dim3(kS / 128, kH, kB), 256, ATTN_SMEM>>>(kmask);

    outproj_mma_kernel<<<dim3((kS * kB) / 128, kD / 64), 256, FGEMM_SMEM>>>(bo, out);
}